// round 13
// baseline (speedup 1.0000x reference)
#include <cuda_runtime.h>
#include <cstdint>

// FixedRadiusNNGraph: B=2, N=8192, F=64, radius=0.3
// R13 experiment: widen per-thread j-coverage 4 -> 8 floats so each warp
// writes 1KB contiguous bursts per output per row (was 512B), probing
// HBM3e row-buffer / write-combining sensitivity. All other axes held at
// the converged config (fused launch, interleaved __stcs, multi-wave).
#define BB 2
#define NN 8192
#define FF 64
#define R2 0.09f

#define TILE_BLOCKS 8192             // (NN/2048 j-tiles=4) * (NN/8 rowgroups=1024) * B=2
#define COPY_BLOCKS 112
#define NPTS   (BB * NN * 3)         // 49,152 floats
#define NFEAT  (BB * NN * FF)        // 1,048,576 floats
#define TAIL_V4 ((NPTS + NFEAT) / 4) // 274,432 float4
#define PTS_V4 (NPTS / 4)            // 12,288 float4

__device__ __forceinline__ void stream_st(float* p, float4 v) {
    __stcs(reinterpret_cast<float4*>(p), v);
}

__global__ __launch_bounds__(256) void frnn_fused_kernel(
    const float* __restrict__ pts,
    const float* __restrict__ feats,
    float* __restrict__ out)
{
    const long long bnn = (long long)BB * NN * NN;
    const int bx = blockIdx.x;

    if (bx >= TILE_BLOCKS) {
        // ---- tail copy: [pts | feats] -> out + 2*bnn, as float4 ----
        const int cb = bx - TILE_BLOCKS;
        float* dst = out + 2 * bnn;
        const float4* src_p = reinterpret_cast<const float4*>(pts);
        const float4* src_f = reinterpret_cast<const float4*>(feats);
        for (int t = cb * 256 + threadIdx.x; t < TAIL_V4; t += COPY_BLOCKS * 256) {
            float4 v = (t < PTS_V4) ? __ldg(src_p + t) : __ldg(src_f + (t - PTS_V4));
            stream_st(dst + 4 * (size_t)t, v);
        }
        return;
    }

    // ---- tile work: block covers 8 i-rows x 2048 j (8 j per thread) ----
    const int jt = bx & 3;                  // 4 j-tiles of 2048
    const int rg = (bx >> 2) & 1023;        // 1024 row-groups
    const int b  = bx >> 12;                // batch
    const int i0 = rg * 8;
    const int j0 = (jt * 256 + threadIdx.x) * 8;

    const float* p = pts + (size_t)b * NN * 3;

    // 8 contiguous j-points: 24 floats = 6 aligned float4 loads (j0 % 8 == 0).
    const float4* jv = reinterpret_cast<const float4*>(p + (size_t)j0 * 3);
    const float4 u0 = __ldg(jv + 0), u1 = __ldg(jv + 1), u2 = __ldg(jv + 2);
    const float4 u3 = __ldg(jv + 3), u4 = __ldg(jv + 4), u5 = __ldg(jv + 5);
    const float qx[8] = {u0.x, u0.w, u1.z, u2.y, u3.x, u3.w, u4.z, u5.y};
    const float qy[8] = {u0.y, u1.x, u1.w, u2.z, u3.y, u4.x, u4.w, u5.z};
    const float qz[8] = {u0.z, u1.y, u2.x, u2.w, u3.z, u4.y, u5.x, u5.w};
    float qn[8];
#pragma unroll
    for (int k = 0; k < 8; k++) qn[k] = qx[k]*qx[k] + qy[k]*qy[k] + qz[k]*qz[k];

    float* adj_out  = out;
    float* dist_out = out + bnn;
    const size_t base = (size_t)b * NN * NN + (size_t)i0 * NN + j0;

    // i-points re-loaded per row from L1 (block-wide broadcast, L1-resident)
    // to keep registers in check at 8 j/thread.
    const float* pi_ptr = p + (size_t)i0 * 3;

#pragma unroll
    for (int ii = 0; ii < 8; ii++) {
        const float x = __ldg(pi_ptr + 3 * ii + 0);
        const float y = __ldg(pi_ptr + 3 * ii + 1);
        const float z = __ldg(pi_ptr + 3 * ii + 2);
        const float pn = x*x + y*y + z*z;

        float dv[8];
#pragma unroll
        for (int k = 0; k < 8; k++)
            dv[k] = (pn + qn[k]) - 2.0f * (x*qx[k] + y*qy[k] + z*qz[k]);

        float4 d0 = make_float4(dv[0], dv[1], dv[2], dv[3]);
        float4 d1 = make_float4(dv[4], dv[5], dv[6], dv[7]);
        float4 a0, a1;
        a0.x = (dv[0] <= R2) ? 1.0f : 0.0f;
        a0.y = (dv[1] <= R2) ? 1.0f : 0.0f;
        a0.z = (dv[2] <= R2) ? 1.0f : 0.0f;
        a0.w = (dv[3] <= R2) ? 1.0f : 0.0f;
        a1.x = (dv[4] <= R2) ? 1.0f : 0.0f;
        a1.y = (dv[5] <= R2) ? 1.0f : 0.0f;
        a1.z = (dv[6] <= R2) ? 1.0f : 0.0f;
        a1.w = (dv[7] <= R2) ? 1.0f : 0.0f;

        const size_t off = base + (size_t)ii * NN;
        // back-to-back 16B stores -> 1KB contiguous warp burst per output
        stream_st(dist_out + off,     d0);
        stream_st(dist_out + off + 4, d1);
        stream_st(adj_out + off,      a0);
        stream_st(adj_out + off + 4,  a1);
    }
}

extern "C" void kernel_launch(void* const* d_in, const int* in_sizes, int n_in,
                              void* d_out, int out_size)
{
    const float* batch_points = (const float*)d_in[0];
    const float* batch_feats  = (const float*)d_in[1];
    // d_in[2] = batch_len: static uniform offsets, unused.

    frnn_fused_kernel<<<TILE_BLOCKS + COPY_BLOCKS, 256>>>(
        batch_points, batch_feats, (float*)d_out);
}

// round 14
// speedup vs baseline: 1.8114x; 1.8114x over previous
#include <cuda_runtime.h>
#include <cstdint>

// FixedRadiusNNGraph: B=2, N=8192, F=64, radius=0.3
// R14: CORRECTED 1KB-warp-burst experiment. R13 failed because j0=tid*8 made
// lanes 32B apart (half-density strided stores -> DRAM 49%). Here every STG
// keeps the proven warp-contiguous shape (lane stride 16B, 512B/warp/store);
// each thread issues two stores 128 floats (=1 warp width) apart, so a warp's
// back-to-back stores cover a contiguous 1KB span per output per row.
#define BB 2
#define NN 8192
#define FF 64
#define R2 0.09f

#define TILE_BLOCKS 8192             // (NN/2048 j-tiles=4) * (NN/8 rowgroups=1024) * B=2
#define COPY_BLOCKS 112
#define NPTS   (BB * NN * 3)         // 49,152 floats
#define NFEAT  (BB * NN * FF)        // 1,048,576 floats
#define TAIL_V4 ((NPTS + NFEAT) / 4) // 274,432 float4
#define PTS_V4 (NPTS / 4)            // 12,288 float4

__device__ __forceinline__ void stream_st(float* p, float4 v) {
    __stcs(reinterpret_cast<float4*>(p), v);
}

__global__ __launch_bounds__(256) void frnn_fused_kernel(
    const float* __restrict__ pts,
    const float* __restrict__ feats,
    float* __restrict__ out)
{
    const long long bnn = (long long)BB * NN * NN;
    const int bx = blockIdx.x;

    if (bx >= TILE_BLOCKS) {
        // ---- tail copy: [pts | feats] -> out + 2*bnn, as float4 ----
        const int cb = bx - TILE_BLOCKS;
        float* dst = out + 2 * bnn;
        const float4* src_p = reinterpret_cast<const float4*>(pts);
        const float4* src_f = reinterpret_cast<const float4*>(feats);
        for (int t = cb * 256 + threadIdx.x; t < TAIL_V4; t += COPY_BLOCKS * 256) {
            float4 v = (t < PTS_V4) ? __ldg(src_p + t) : __ldg(src_f + (t - PTS_V4));
            stream_st(dst + 4 * (size_t)t, v);
        }
        return;
    }

    // ---- tile work: block covers 8 i-rows x 2048 j ----
    // Warp w owns j-span [jt*2048 + w*256, +256): lane handles j0 and j0+128.
    const int jt   = bx & 3;                 // 4 j-tiles of 2048
    const int rg   = (bx >> 2) & 1023;       // 1024 row-groups
    const int b    = bx >> 12;               // batch
    const int i0   = rg * 8;
    const int wid  = threadIdx.x >> 5;
    const int lane = threadIdx.x & 31;
    const int j0   = jt * 2048 + wid * 256 + lane * 4;   // first quad
    const int j1   = j0 + 128;                           // second quad (adjacent 512B chunk)

    const float* p = pts + (size_t)b * NN * 3;

    // Quad A: 4 contiguous j-points (12 floats = 3 aligned float4 loads).
    const float4* jva = reinterpret_cast<const float4*>(p + (size_t)j0 * 3);
    const float4 v0 = __ldg(jva + 0), v1 = __ldg(jva + 1), v2 = __ldg(jva + 2);
    const float ax0 = v0.x, ay0 = v0.y, az0 = v0.z;
    const float ax1 = v0.w, ay1 = v1.x, az1 = v1.y;
    const float ax2 = v1.z, ay2 = v1.w, az2 = v2.x;
    const float ax3 = v2.y, ay3 = v2.z, az3 = v2.w;
    const float an0 = ax0*ax0 + ay0*ay0 + az0*az0;
    const float an1 = ax1*ax1 + ay1*ay1 + az1*az1;
    const float an2 = ax2*ax2 + ay2*ay2 + az2*az2;
    const float an3 = ax3*ax3 + ay3*ay3 + az3*az3;

    // Quad B.
    const float4* jvb = reinterpret_cast<const float4*>(p + (size_t)j1 * 3);
    const float4 s0 = __ldg(jvb + 0), s1 = __ldg(jvb + 1), s2 = __ldg(jvb + 2);
    const float bx0 = s0.x, by0 = s0.y, bz0 = s0.z;
    const float bx1 = s0.w, by1 = s1.x, bz1 = s1.y;
    const float bx2 = s1.z, by2 = s1.w, bz2 = s2.x;
    const float bx3 = s2.y, by3 = s2.z, bz3 = s2.w;
    const float bn0 = bx0*bx0 + by0*by0 + bz0*bz0;
    const float bn1 = bx1*bx1 + by1*by1 + bz1*bz1;
    const float bn2 = bx2*bx2 + by2*by2 + bz2*bz2;
    const float bn3 = bx3*bx3 + by3*by3 + bz3*bz3;

    float* adj_out  = out;
    float* dist_out = out + bnn;
    const size_t base = (size_t)b * NN * NN + (size_t)i0 * NN + j0;

    // i-points re-loaded per row from L1 (block-wide broadcast) to cap regs.
    const float* pi_ptr = p + (size_t)i0 * 3;

#pragma unroll
    for (int ii = 0; ii < 8; ii++) {
        const float x = __ldg(pi_ptr + 3 * ii + 0);
        const float y = __ldg(pi_ptr + 3 * ii + 1);
        const float z = __ldg(pi_ptr + 3 * ii + 2);
        const float pn = x*x + y*y + z*z;

        float4 dA, dB;
        dA.x = (pn + an0) - 2.0f * (x*ax0 + y*ay0 + z*az0);
        dA.y = (pn + an1) - 2.0f * (x*ax1 + y*ay1 + z*az1);
        dA.z = (pn + an2) - 2.0f * (x*ax2 + y*ay2 + z*az2);
        dA.w = (pn + an3) - 2.0f * (x*ax3 + y*ay3 + z*az3);
        dB.x = (pn + bn0) - 2.0f * (x*bx0 + y*by0 + z*bz0);
        dB.y = (pn + bn1) - 2.0f * (x*bx1 + y*by1 + z*bz1);
        dB.z = (pn + bn2) - 2.0f * (x*bx2 + y*by2 + z*bz2);
        dB.w = (pn + bn3) - 2.0f * (x*bx3 + y*by3 + z*bz3);

        float4 aA, aB;
        aA.x = (dA.x <= R2) ? 1.0f : 0.0f;
        aA.y = (dA.y <= R2) ? 1.0f : 0.0f;
        aA.z = (dA.z <= R2) ? 1.0f : 0.0f;
        aA.w = (dA.w <= R2) ? 1.0f : 0.0f;
        aB.x = (dB.x <= R2) ? 1.0f : 0.0f;
        aB.y = (dB.y <= R2) ? 1.0f : 0.0f;
        aB.z = (dB.z <= R2) ? 1.0f : 0.0f;
        aB.w = (dB.w <= R2) ? 1.0f : 0.0f;

        const size_t off = base + (size_t)ii * NN;
        // two warp-contiguous 512B stores, adjacent -> 1KB warp burst
        stream_st(dist_out + off,       dA);
        stream_st(dist_out + off + 128, dB);
        stream_st(adj_out + off,        aA);
        stream_st(adj_out + off + 128,  aB);
    }
}

extern "C" void kernel_launch(void* const* d_in, const int* in_sizes, int n_in,
                              void* d_out, int out_size)
{
    const float* batch_points = (const float*)d_in[0];
    const float* batch_feats  = (const float*)d_in[1];
    // d_in[2] = batch_len: static uniform offsets, unused.

    frnn_fused_kernel<<<TILE_BLOCKS + COPY_BLOCKS, 256>>>(
        batch_points, batch_feats, (float*)d_out);
}

// round 15
// speedup vs baseline: 1.8126x; 1.0007x over previous
#include <cuda_runtime.h>
#include <cstdint>

// FixedRadiusNNGraph: B=2, N=8192, F=64, radius=0.3
// R15: confirmation re-bench of the 1KB-warp-burst layout (identical source
// to R14). R14 produced the best kernel time of 15 rounds (144.67us, DRAM
// 89.3%, 7081 GB/s vs prior band 145.15-146.94us / 88.0-89.2%); end-to-end
// was masked by 1.6us of harness jitter (gap varies 0.16-1.6us run to run).
// Every STG is warp-contiguous (lane stride 16B, 512B/warp); each thread
// issues two stores 128 floats apart -> each warp covers a contiguous 1KB
// span per output per row (HBM3e row-buffer-friendly).
#define BB 2
#define NN 8192
#define FF 64
#define R2 0.09f

#define TILE_BLOCKS 8192             // (NN/2048 j-tiles=4) * (NN/8 rowgroups=1024) * B=2
#define COPY_BLOCKS 112
#define NPTS   (BB * NN * 3)         // 49,152 floats
#define NFEAT  (BB * NN * FF)        // 1,048,576 floats
#define TAIL_V4 ((NPTS + NFEAT) / 4) // 274,432 float4
#define PTS_V4 (NPTS / 4)            // 12,288 float4

__device__ __forceinline__ void stream_st(float* p, float4 v) {
    __stcs(reinterpret_cast<float4*>(p), v);
}

__global__ __launch_bounds__(256) void frnn_fused_kernel(
    const float* __restrict__ pts,
    const float* __restrict__ feats,
    float* __restrict__ out)
{
    const long long bnn = (long long)BB * NN * NN;
    const int bx = blockIdx.x;

    if (bx >= TILE_BLOCKS) {
        // ---- tail copy: [pts | feats] -> out + 2*bnn, as float4 ----
        const int cb = bx - TILE_BLOCKS;
        float* dst = out + 2 * bnn;
        const float4* src_p = reinterpret_cast<const float4*>(pts);
        const float4* src_f = reinterpret_cast<const float4*>(feats);
        for (int t = cb * 256 + threadIdx.x; t < TAIL_V4; t += COPY_BLOCKS * 256) {
            float4 v = (t < PTS_V4) ? __ldg(src_p + t) : __ldg(src_f + (t - PTS_V4));
            stream_st(dst + 4 * (size_t)t, v);
        }
        return;
    }

    // ---- tile work: block covers 8 i-rows x 2048 j ----
    // Warp w owns j-span [jt*2048 + w*256, +256): lane handles j0 and j0+128.
    const int jt   = bx & 3;                 // 4 j-tiles of 2048
    const int rg   = (bx >> 2) & 1023;       // 1024 row-groups
    const int b    = bx >> 12;               // batch
    const int i0   = rg * 8;
    const int wid  = threadIdx.x >> 5;
    const int lane = threadIdx.x & 31;
    const int j0   = jt * 2048 + wid * 256 + lane * 4;   // first quad
    const int j1   = j0 + 128;                           // second quad (adjacent 512B chunk)

    const float* p = pts + (size_t)b * NN * 3;

    // Quad A: 4 contiguous j-points (12 floats = 3 aligned float4 loads).
    const float4* jva = reinterpret_cast<const float4*>(p + (size_t)j0 * 3);
    const float4 v0 = __ldg(jva + 0), v1 = __ldg(jva + 1), v2 = __ldg(jva + 2);
    const float ax0 = v0.x, ay0 = v0.y, az0 = v0.z;
    const float ax1 = v0.w, ay1 = v1.x, az1 = v1.y;
    const float ax2 = v1.z, ay2 = v1.w, az2 = v2.x;
    const float ax3 = v2.y, ay3 = v2.z, az3 = v2.w;
    const float an0 = ax0*ax0 + ay0*ay0 + az0*az0;
    const float an1 = ax1*ax1 + ay1*ay1 + az1*az1;
    const float an2 = ax2*ax2 + ay2*ay2 + az2*az2;
    const float an3 = ax3*ax3 + ay3*ay3 + az3*az3;

    // Quad B.
    const float4* jvb = reinterpret_cast<const float4*>(p + (size_t)j1 * 3);
    const float4 s0 = __ldg(jvb + 0), s1 = __ldg(jvb + 1), s2 = __ldg(jvb + 2);
    const float bx0 = s0.x, by0 = s0.y, bz0 = s0.z;
    const float bx1 = s0.w, by1 = s1.x, bz1 = s1.y;
    const float bx2 = s1.z, by2 = s1.w, bz2 = s2.x;
    const float bx3 = s2.y, by3 = s2.z, bz3 = s2.w;
    const float bn0 = bx0*bx0 + by0*by0 + bz0*bz0;
    const float bn1 = bx1*bx1 + by1*by1 + bz1*bz1;
    const float bn2 = bx2*bx2 + by2*by2 + bz2*bz2;
    const float bn3 = bx3*bx3 + by3*by3 + bz3*bz3;

    float* adj_out  = out;
    float* dist_out = out + bnn;
    const size_t base = (size_t)b * NN * NN + (size_t)i0 * NN + j0;

    // i-points re-loaded per row from L1 (block-wide broadcast) to cap regs.
    const float* pi_ptr = p + (size_t)i0 * 3;

#pragma unroll
    for (int ii = 0; ii < 8; ii++) {
        const float x = __ldg(pi_ptr + 3 * ii + 0);
        const float y = __ldg(pi_ptr + 3 * ii + 1);
        const float z = __ldg(pi_ptr + 3 * ii + 2);
        const float pn = x*x + y*y + z*z;

        float4 dA, dB;
        dA.x = (pn + an0) - 2.0f * (x*ax0 + y*ay0 + z*az0);
        dA.y = (pn + an1) - 2.0f * (x*ax1 + y*ay1 + z*az1);
        dA.z = (pn + an2) - 2.0f * (x*ax2 + y*ay2 + z*az2);
        dA.w = (pn + an3) - 2.0f * (x*ax3 + y*ay3 + z*az3);
        dB.x = (pn + bn0) - 2.0f * (x*bx0 + y*by0 + z*bz0);
        dB.y = (pn + bn1) - 2.0f * (x*bx1 + y*by1 + z*bz1);
        dB.z = (pn + bn2) - 2.0f * (x*bx2 + y*by2 + z*bz2);
        dB.w = (pn + bn3) - 2.0f * (x*bx3 + y*by3 + z*bz3);

        float4 aA, aB;
        aA.x = (dA.x <= R2) ? 1.0f : 0.0f;
        aA.y = (dA.y <= R2) ? 1.0f : 0.0f;
        aA.z = (dA.z <= R2) ? 1.0f : 0.0f;
        aA.w = (dA.w <= R2) ? 1.0f : 0.0f;
        aB.x = (dB.x <= R2) ? 1.0f : 0.0f;
        aB.y = (dB.y <= R2) ? 1.0f : 0.0f;
        aB.z = (dB.z <= R2) ? 1.0f : 0.0f;
        aB.w = (dB.w <= R2) ? 1.0f : 0.0f;

        const size_t off = base + (size_t)ii * NN;
        // two warp-contiguous 512B stores, adjacent -> 1KB warp burst
        stream_st(dist_out + off,       dA);
        stream_st(dist_out + off + 128, dB);
        stream_st(adj_out + off,        aA);
        stream_st(adj_out + off + 128,  aB);
    }
}

extern "C" void kernel_launch(void* const* d_in, const int* in_sizes, int n_in,
                              void* d_out, int out_size)
{
    const float* batch_points = (const float*)d_in[0];
    const float* batch_feats  = (const float*)d_in[1];
    // d_in[2] = batch_len: static uniform offsets, unused.

    frnn_fused_kernel<<<TILE_BLOCKS + COPY_BLOCKS, 256>>>(
        batch_points, batch_feats, (float*)d_out);
}

// round 16
// speedup vs baseline: 1.8178x; 1.0029x over previous
#include <cuda_runtime.h>
#include <cstdint>

// FixedRadiusNNGraph: B=2, N=8192, F=64, radius=0.3
// FINAL — 1KB-warp-burst layout, converged at the DRAM-write roofline.
// Kernel time 144.7-145.3us (best measured of 16 rounds; 4-float config
// measured 145.2-146.9us over 7 samples). DRAM 88.9-89.3%, ~7.05-7.08TB/s
// on the mandatory 1.078GB store stream => ~99% of attainable write rate.
// Every STG is warp-contiguous (lane stride 16B, 512B/warp); each thread
// issues two stores 128 floats apart so each warp covers a contiguous 1KB
// span per output per row (HBM3e row-buffer-friendly).
// Exhausted axes: store hint / occupancy / split-streams NEUTRAL; persistent
// grid -17%; strided stores -45%; launch fusion +6.5us; 1KB burst +~0.6us.
#define BB 2
#define NN 8192
#define FF 64
#define R2 0.09f

#define TILE_BLOCKS 8192             // (NN/2048 j-tiles=4) * (NN/8 rowgroups=1024) * B=2
#define COPY_BLOCKS 112
#define NPTS   (BB * NN * 3)         // 49,152 floats
#define NFEAT  (BB * NN * FF)        // 1,048,576 floats
#define TAIL_V4 ((NPTS + NFEAT) / 4) // 274,432 float4
#define PTS_V4 (NPTS / 4)            // 12,288 float4

__device__ __forceinline__ void stream_st(float* p, float4 v) {
    __stcs(reinterpret_cast<float4*>(p), v);
}

__global__ __launch_bounds__(256) void frnn_fused_kernel(
    const float* __restrict__ pts,
    const float* __restrict__ feats,
    float* __restrict__ out)
{
    const long long bnn = (long long)BB * NN * NN;
    const int bx = blockIdx.x;

    if (bx >= TILE_BLOCKS) {
        // ---- tail copy: [pts | feats] -> out + 2*bnn, as float4 ----
        const int cb = bx - TILE_BLOCKS;
        float* dst = out + 2 * bnn;
        const float4* src_p = reinterpret_cast<const float4*>(pts);
        const float4* src_f = reinterpret_cast<const float4*>(feats);
        for (int t = cb * 256 + threadIdx.x; t < TAIL_V4; t += COPY_BLOCKS * 256) {
            float4 v = (t < PTS_V4) ? __ldg(src_p + t) : __ldg(src_f + (t - PTS_V4));
            stream_st(dst + 4 * (size_t)t, v);
        }
        return;
    }

    // ---- tile work: block covers 8 i-rows x 2048 j ----
    // Warp w owns j-span [jt*2048 + w*256, +256): lane handles j0 and j0+128.
    const int jt   = bx & 3;                 // 4 j-tiles of 2048
    const int rg   = (bx >> 2) & 1023;       // 1024 row-groups
    const int b    = bx >> 12;               // batch
    const int i0   = rg * 8;
    const int wid  = threadIdx.x >> 5;
    const int lane = threadIdx.x & 31;
    const int j0   = jt * 2048 + wid * 256 + lane * 4;   // first quad
    const int j1   = j0 + 128;                           // second quad (adjacent 512B chunk)

    const float* p = pts + (size_t)b * NN * 3;

    // Quad A: 4 contiguous j-points (12 floats = 3 aligned float4 loads).
    const float4* jva = reinterpret_cast<const float4*>(p + (size_t)j0 * 3);
    const float4 v0 = __ldg(jva + 0), v1 = __ldg(jva + 1), v2 = __ldg(jva + 2);
    const float ax0 = v0.x, ay0 = v0.y, az0 = v0.z;
    const float ax1 = v0.w, ay1 = v1.x, az1 = v1.y;
    const float ax2 = v1.z, ay2 = v1.w, az2 = v2.x;
    const float ax3 = v2.y, ay3 = v2.z, az3 = v2.w;
    const float an0 = ax0*ax0 + ay0*ay0 + az0*az0;
    const float an1 = ax1*ax1 + ay1*ay1 + az1*az1;
    const float an2 = ax2*ax2 + ay2*ay2 + az2*az2;
    const float an3 = ax3*ax3 + ay3*ay3 + az3*az3;

    // Quad B.
    const float4* jvb = reinterpret_cast<const float4*>(p + (size_t)j1 * 3);
    const float4 s0 = __ldg(jvb + 0), s1 = __ldg(jvb + 1), s2 = __ldg(jvb + 2);
    const float bx0 = s0.x, by0 = s0.y, bz0 = s0.z;
    const float bx1 = s0.w, by1 = s1.x, bz1 = s1.y;
    const float bx2 = s1.z, by2 = s1.w, bz2 = s2.x;
    const float bx3 = s2.y, by3 = s2.z, bz3 = s2.w;
    const float bn0 = bx0*bx0 + by0*by0 + bz0*bz0;
    const float bn1 = bx1*bx1 + by1*by1 + bz1*bz1;
    const float bn2 = bx2*bx2 + by2*by2 + bz2*bz2;
    const float bn3 = bx3*bx3 + by3*by3 + bz3*bz3;

    float* adj_out  = out;
    float* dist_out = out + bnn;
    const size_t base = (size_t)b * NN * NN + (size_t)i0 * NN + j0;

    // i-points re-loaded per row from L1 (block-wide broadcast) to cap regs.
    const float* pi_ptr = p + (size_t)i0 * 3;

#pragma unroll
    for (int ii = 0; ii < 8; ii++) {
        const float x = __ldg(pi_ptr + 3 * ii + 0);
        const float y = __ldg(pi_ptr + 3 * ii + 1);
        const float z = __ldg(pi_ptr + 3 * ii + 2);
        const float pn = x*x + y*y + z*z;

        float4 dA, dB;
        dA.x = (pn + an0) - 2.0f * (x*ax0 + y*ay0 + z*az0);
        dA.y = (pn + an1) - 2.0f * (x*ax1 + y*ay1 + z*az1);
        dA.z = (pn + an2) - 2.0f * (x*ax2 + y*ay2 + z*az2);
        dA.w = (pn + an3) - 2.0f * (x*ax3 + y*ay3 + z*az3);
        dB.x = (pn + bn0) - 2.0f * (x*bx0 + y*by0 + z*bz0);
        dB.y = (pn + bn1) - 2.0f * (x*bx1 + y*by1 + z*bz1);
        dB.z = (pn + bn2) - 2.0f * (x*bx2 + y*by2 + z*bz2);
        dB.w = (pn + bn3) - 2.0f * (x*bx3 + y*by3 + z*bz3);

        float4 aA, aB;
        aA.x = (dA.x <= R2) ? 1.0f : 0.0f;
        aA.y = (dA.y <= R2) ? 1.0f : 0.0f;
        aA.z = (dA.z <= R2) ? 1.0f : 0.0f;
        aA.w = (dA.w <= R2) ? 1.0f : 0.0f;
        aB.x = (dB.x <= R2) ? 1.0f : 0.0f;
        aB.y = (dB.y <= R2) ? 1.0f : 0.0f;
        aB.z = (dB.z <= R2) ? 1.0f : 0.0f;
        aB.w = (dB.w <= R2) ? 1.0f : 0.0f;

        const size_t off = base + (size_t)ii * NN;
        // two warp-contiguous 512B stores, adjacent -> 1KB warp burst
        stream_st(dist_out + off,       dA);
        stream_st(dist_out + off + 128, dB);
        stream_st(adj_out + off,        aA);
        stream_st(adj_out + off + 128,  aB);
    }
}

extern "C" void kernel_launch(void* const* d_in, const int* in_sizes, int n_in,
                              void* d_out, int out_size)
{
    const float* batch_points = (const float*)d_in[0];
    const float* batch_feats  = (const float*)d_in[1];
    // d_in[2] = batch_len: static uniform offsets, unused.

    frnn_fused_kernel<<<TILE_BLOCKS + COPY_BLOCKS, 256>>>(
        batch_points, batch_feats, (float*)d_out);
}

// round 17
// speedup vs baseline: 1.8206x; 1.0015x over previous
#include <cuda_runtime.h>
#include <cstdint>

// FixedRadiusNNGraph: B=2, N=8192, F=64, radius=0.3
// FINAL — 1KB-warp-burst layout, converged at the DRAM-write roofline.
// Kernel time {144.42, 144.67, 145.28}us over 3 samples (old 4-float config:
// 145.15-146.94us over 7). DRAM 88.9-89.4%, 7.05-7.09TB/s on the mandatory
// 1.078GB store stream => ~99% of attainable write rate. Grid = 14.0 waves
// at 4 blocks/SM (no partial-wave tail waste).
// Every STG is warp-contiguous (lane stride 16B, 512B/warp); each thread
// issues two stores 128 floats apart so each warp covers a contiguous 1KB
// span per output per row (HBM3e row-buffer-friendly).
// Exhausted axes: store hint / occupancy / split-streams NEUTRAL; persistent
// grid -17%; strided stores -45%; launch fusion +6.5us; 1KB burst +0.8us.
#define BB 2
#define NN 8192
#define FF 64
#define R2 0.09f

#define TILE_BLOCKS 8192             // (NN/2048 j-tiles=4) * (NN/8 rowgroups=1024) * B=2
#define COPY_BLOCKS 112
#define NPTS   (BB * NN * 3)         // 49,152 floats
#define NFEAT  (BB * NN * FF)        // 1,048,576 floats
#define TAIL_V4 ((NPTS + NFEAT) / 4) // 274,432 float4
#define PTS_V4 (NPTS / 4)            // 12,288 float4

__device__ __forceinline__ void stream_st(float* p, float4 v) {
    __stcs(reinterpret_cast<float4*>(p), v);
}

__global__ __launch_bounds__(256) void frnn_fused_kernel(
    const float* __restrict__ pts,
    const float* __restrict__ feats,
    float* __restrict__ out)
{
    const long long bnn = (long long)BB * NN * NN;
    const int bx = blockIdx.x;

    if (bx >= TILE_BLOCKS) {
        // ---- tail copy: [pts | feats] -> out + 2*bnn, as float4 ----
        const int cb = bx - TILE_BLOCKS;
        float* dst = out + 2 * bnn;
        const float4* src_p = reinterpret_cast<const float4*>(pts);
        const float4* src_f = reinterpret_cast<const float4*>(feats);
        for (int t = cb * 256 + threadIdx.x; t < TAIL_V4; t += COPY_BLOCKS * 256) {
            float4 v = (t < PTS_V4) ? __ldg(src_p + t) : __ldg(src_f + (t - PTS_V4));
            stream_st(dst + 4 * (size_t)t, v);
        }
        return;
    }

    // ---- tile work: block covers 8 i-rows x 2048 j ----
    // Warp w owns j-span [jt*2048 + w*256, +256): lane handles j0 and j0+128.
    const int jt   = bx & 3;                 // 4 j-tiles of 2048
    const int rg   = (bx >> 2) & 1023;       // 1024 row-groups
    const int b    = bx >> 12;               // batch
    const int i0   = rg * 8;
    const int wid  = threadIdx.x >> 5;
    const int lane = threadIdx.x & 31;
    const int j0   = jt * 2048 + wid * 256 + lane * 4;   // first quad
    const int j1   = j0 + 128;                           // second quad (adjacent 512B chunk)

    const float* p = pts + (size_t)b * NN * 3;

    // Quad A: 4 contiguous j-points (12 floats = 3 aligned float4 loads).
    const float4* jva = reinterpret_cast<const float4*>(p + (size_t)j0 * 3);
    const float4 v0 = __ldg(jva + 0), v1 = __ldg(jva + 1), v2 = __ldg(jva + 2);
    const float ax0 = v0.x, ay0 = v0.y, az0 = v0.z;
    const float ax1 = v0.w, ay1 = v1.x, az1 = v1.y;
    const float ax2 = v1.z, ay2 = v1.w, az2 = v2.x;
    const float ax3 = v2.y, ay3 = v2.z, az3 = v2.w;
    const float an0 = ax0*ax0 + ay0*ay0 + az0*az0;
    const float an1 = ax1*ax1 + ay1*ay1 + az1*az1;
    const float an2 = ax2*ax2 + ay2*ay2 + az2*az2;
    const float an3 = ax3*ax3 + ay3*ay3 + az3*az3;

    // Quad B.
    const float4* jvb = reinterpret_cast<const float4*>(p + (size_t)j1 * 3);
    const float4 s0 = __ldg(jvb + 0), s1 = __ldg(jvb + 1), s2 = __ldg(jvb + 2);
    const float bx0 = s0.x, by0 = s0.y, bz0 = s0.z;
    const float bx1 = s0.w, by1 = s1.x, bz1 = s1.y;
    const float bx2 = s1.z, by2 = s1.w, bz2 = s2.x;
    const float bx3 = s2.y, by3 = s2.z, bz3 = s2.w;
    const float bn0 = bx0*bx0 + by0*by0 + bz0*bz0;
    const float bn1 = bx1*bx1 + by1*by1 + bz1*bz1;
    const float bn2 = bx2*bx2 + by2*by2 + bz2*bz2;
    const float bn3 = bx3*bx3 + by3*by3 + bz3*bz3;

    float* adj_out  = out;
    float* dist_out = out + bnn;
    const size_t base = (size_t)b * NN * NN + (size_t)i0 * NN + j0;

    // i-points re-loaded per row from L1 (block-wide broadcast) to cap regs.
    const float* pi_ptr = p + (size_t)i0 * 3;

#pragma unroll
    for (int ii = 0; ii < 8; ii++) {
        const float x = __ldg(pi_ptr + 3 * ii + 0);
        const float y = __ldg(pi_ptr + 3 * ii + 1);
        const float z = __ldg(pi_ptr + 3 * ii + 2);
        const float pn = x*x + y*y + z*z;

        float4 dA, dB;
        dA.x = (pn + an0) - 2.0f * (x*ax0 + y*ay0 + z*az0);
        dA.y = (pn + an1) - 2.0f * (x*ax1 + y*ay1 + z*az1);
        dA.z = (pn + an2) - 2.0f * (x*ax2 + y*ay2 + z*az2);
        dA.w = (pn + an3) - 2.0f * (x*ax3 + y*ay3 + z*az3);
        dB.x = (pn + bn0) - 2.0f * (x*bx0 + y*by0 + z*bz0);
        dB.y = (pn + bn1) - 2.0f * (x*bx1 + y*by1 + z*bz1);
        dB.z = (pn + bn2) - 2.0f * (x*bx2 + y*by2 + z*bz2);
        dB.w = (pn + bn3) - 2.0f * (x*bx3 + y*by3 + z*bz3);

        float4 aA, aB;
        aA.x = (dA.x <= R2) ? 1.0f : 0.0f;
        aA.y = (dA.y <= R2) ? 1.0f : 0.0f;
        aA.z = (dA.z <= R2) ? 1.0f : 0.0f;
        aA.w = (dA.w <= R2) ? 1.0f : 0.0f;
        aB.x = (dB.x <= R2) ? 1.0f : 0.0f;
        aB.y = (dB.y <= R2) ? 1.0f : 0.0f;
        aB.z = (dB.z <= R2) ? 1.0f : 0.0f;
        aB.w = (dB.w <= R2) ? 1.0f : 0.0f;

        const size_t off = base + (size_t)ii * NN;
        // two warp-contiguous 512B stores, adjacent -> 1KB warp burst
        stream_st(dist_out + off,       dA);
        stream_st(dist_out + off + 128, dB);
        stream_st(adj_out + off,        aA);
        stream_st(adj_out + off + 128,  aB);
    }
}

extern "C" void kernel_launch(void* const* d_in, const int* in_sizes, int n_in,
                              void* d_out, int out_size)
{
    const float* batch_points = (const float*)d_in[0];
    const float* batch_feats  = (const float*)d_in[1];
    // d_in[2] = batch_len: static uniform offsets, unused.

    frnn_fused_kernel<<<TILE_BLOCKS + COPY_BLOCKS, 256>>>(
        batch_points, batch_feats, (float*)d_out);
}